// round 5
// baseline (speedup 1.0000x reference)
#include <cuda_runtime.h>
#include <cuda.h>
#include <cuda_bf16.h>
#include <math.h>
#include <stdint.h>
#include <dlfcn.h>

// ---------------- problem constants ----------------
#define QN    16
#define C0N   8
#define C1N   4
#define K3T   125
#define NCH   320
#define VOX   512
#define GK    8
#define NSPL  24
#define NCHUNK 625          // 125 taps * 5 ci-blocks of 64

// smem stage layout (bytes) after 1KB header
#define SOFF_AHI 0
#define SOFF_ALO 16384
#define SOFF_BHI 32768
#define SOFF_BLO 65536
#define STAGE_BYTES 98304
#define HDR 1024
#define SMEM_TOTAL (HDR + 2 * STAGE_BYTES)

// ---------------- device globals ----------------
__device__ __nv_bfloat16 gA_hi[(size_t)K3T * NCH * NCH];   // [tap][och][ci]
__device__ __nv_bfloat16 gA_lo[(size_t)K3T * NCH * NCH];
__device__ __nv_bfloat16 gXp_hi[1728 * NCH];               // [pz*144+py*12+px][ci]
__device__ __nv_bfloat16 gXp_lo[1728 * NCH];
__device__ float g_part[(size_t)NSPL * 6 * 128 * 256];     // [s][mt*2+nt][128][256]

// ---------------- PTX helpers ----------------
__device__ __forceinline__ uint32_t smem_u32(const void* p) {
    uint32_t a;
    asm("{ .reg .u64 t; cvta.to.shared.u64 t, %1; cvt.u32.u64 %0, t; }" : "=r"(a) : "l"(p));
    return a;
}
__device__ __forceinline__ void ldm4(uint32_t& r0, uint32_t& r1, uint32_t& r2,
                                     uint32_t& r3, uint32_t addr) {
    asm volatile("ldmatrix.sync.aligned.m8n8.x4.shared.b16 {%0,%1,%2,%3}, [%4];"
                 : "=r"(r0), "=r"(r1), "=r"(r2), "=r"(r3) : "r"(addr));
}
__device__ __forceinline__ void mma16816(float* c, uint32_t a0, uint32_t a1,
                                         uint32_t a2, uint32_t a3,
                                         uint32_t b0, uint32_t b1) {
    asm volatile("mma.sync.aligned.m16n8k16.row.col.f32.bf16.bf16.f32 "
                 "{%0,%1,%2,%3}, {%4,%5,%6,%7}, {%8,%9}, {%0,%1,%2,%3};"
                 : "+f"(c[0]), "+f"(c[1]), "+f"(c[2]), "+f"(c[3])
                 : "r"(a0), "r"(a1), "r"(a2), "r"(a3), "r"(b0), "r"(b1));
}
__device__ __forceinline__ void mbar_init(uint32_t a, uint32_t n) {
    asm volatile("mbarrier.init.shared.b64 [%0], %1;" :: "r"(a), "r"(n) : "memory");
}
__device__ __forceinline__ void mbar_expect_tx(uint32_t a, uint32_t bytes) {
    asm volatile("mbarrier.arrive.expect_tx.shared.b64 _, [%0], %1;"
                 :: "r"(a), "r"(bytes) : "memory");
}
__device__ __forceinline__ void mbar_wait(uint32_t mbar, uint32_t parity) {
    uint32_t done;
    asm volatile("{\n\t.reg .pred p;\n\t"
                 "mbarrier.try_wait.parity.acquire.cta.shared::cta.b64 p, [%1], %2;\n\t"
                 "selp.b32 %0, 1, 0, p;\n\t}"
                 : "=r"(done) : "r"(mbar), "r"(parity) : "memory");
    if (!done) {
        asm volatile("{\n\t.reg .pred P1;\n\t"
                     "W%=:\n\t"
                     "mbarrier.try_wait.parity.acquire.cta.shared::cta.b64 P1, [%0], %1, 0x989680;\n\t"
                     "@P1 bra.uni D%=;\n\t"
                     "bra.uni W%=;\n\t"
                     "D%=:\n\t}"
                     :: "r"(mbar), "r"(parity) : "memory");
    }
}
__device__ __forceinline__ void tma3d(uint32_t dst, const void* map,
                                      int c0, int c1, int c2, uint32_t mbar) {
    asm volatile("cp.async.bulk.tensor.3d.shared::cta.global.tile.mbarrier::complete_tx::bytes "
                 "[%0], [%1, {%2, %3, %4}], [%5];"
                 :: "r"(dst), "l"(map), "r"(c0), "r"(c1), "r"(c2), "r"(mbar) : "memory");
}
__device__ __forceinline__ void tma4d(uint32_t dst, const void* map,
                                      int c0, int c1, int c2, int c3, uint32_t mbar) {
    asm volatile("cp.async.bulk.tensor.4d.shared::cta.global.tile.mbarrier::complete_tx::bytes "
                 "[%0], [%1, {%2, %3, %4, %5}], [%6];"
                 :: "r"(dst), "l"(map), "r"(c0), "r"(c1), "r"(c2), "r"(c3), "r"(mbar) : "memory");
}

// ---------------------------------------------------------------------------
// Kernel 1: x -> transposed + halo-padded bf16 hi/lo [1728 pos][320 ci]
// ---------------------------------------------------------------------------
__global__ void xpad_kernel(const float* __restrict__ x) {
    int i = blockIdx.x * blockDim.x + threadIdx.x;
    if (i >= 1728 * NCH) return;
    int ci = i % NCH, ppos = i / NCH;
    int px = ppos % 12, py = (ppos / 12) % 12, pz = ppos / 144;
    int z = pz - 2, y = py - 2, xx = px - 2;
    float v = 0.f;
    if ((unsigned)z < 8 && (unsigned)y < 8 && (unsigned)xx < 8)
        v = x[ci * VOX + z * 64 + y * 8 + xx];
    __nv_bfloat16 h = __float2bfloat16(v);
    gXp_hi[i] = h;
    gXp_lo[i] = __float2bfloat16(v - __bfloat162float(h));
}

// ---------------------------------------------------------------------------
// Kernel 2: build equivariant kernel -> gA_hi/gA_lo [tap][och][ci] bf16 split.
// ---------------------------------------------------------------------------
__global__ void build_kern_kernel(const float* __restrict__ q_in,
                                  const float* __restrict__ q_out,
                                  const float* __restrict__ w_ss,
                                  const float* __restrict__ w_vs,
                                  const float* __restrict__ w_sv,
                                  const float* __restrict__ w_vv0,
                                  const float* __restrict__ w_vv1) {
    int idx = blockIdx.x * blockDim.x + threadIdx.x;
    if (idx >= QN * QN * K3T) return;
    int t = idx % K3T;
    int q = (idx / K3T) % QN;
    int p = idx / (K3T * QN);
    int path = blockIdx.y;

    int dz = t / 25, dy = (t / 5) % 5, dx = t % 5;
    float v0 = (float)(dz - 2) - (q_out[p * 3 + 0] - q_in[q * 3 + 0]);
    float v1 = (float)(dy - 2) - (q_out[p * 3 + 1] - q_in[q * 3 + 1]);
    float v2 = (float)(dx - 2) - (q_out[p * 3 + 2] - q_in[q * 3 + 2]);
    float r  = sqrtf(v0 * v0 + v1 * v1 + v2 * v2);
    float inv = (r > 1e-6f) ? (1.0f / r) : 0.0f;
    float u[3] = {v0 * inv, v1 * inv, v2 * inv};

    const float sigma = 5.5f / 7.0f;
    float R[GK];
#pragma unroll
    for (int g = 0; g < GK; g++) {
        float d = (r - sigma * (float)g) / sigma;
        R[g] = expf(-0.5f * d * d);
    }

    float cross[3][3];
    cross[0][0] = 0.f;    cross[0][1] = -u[2];  cross[0][2] =  u[1];
    cross[1][0] =  u[2];  cross[1][1] = 0.f;    cross[1][2] = -u[0];
    cross[2][0] = -u[1];  cross[2][1] =  u[0];  cross[2][2] = 0.f;

#define KSTORE(row, col, val) do {                                         \
    float _v = (val);                                                      \
    __nv_bfloat16 _h = __float2bfloat16(_v);                               \
    __nv_bfloat16 _l = __float2bfloat16(_v - __bfloat162float(_h));        \
    size_t _o = ((size_t)t * NCH + ((row) * QN + p)) * NCH + ((col) * QN + q); \
    gA_hi[_o] = _h; gA_lo[_o] = _l; } while (0)

    if (path == 0) {
        for (int a = 0; a < C0N; a++)
            for (int c = 0; c < C0N; c++) {
                float s = 0.f;
#pragma unroll
                for (int g = 0; g < GK; g++) s += w_ss[(a * C0N + c) * GK + g] * R[g];
                KSTORE(a, c, s);
            }
    } else if (path == 1) {
        for (int a = 0; a < C0N; a++)
            for (int c = 0; c < C1N; c++) {
                float s = 0.f;
#pragma unroll
                for (int g = 0; g < GK; g++) s += w_sv[(a * C1N + c) * GK + g] * R[g];
#pragma unroll
                for (int j = 0; j < 3; j++) KSTORE(a, 8 + c * 3 + j, s * u[j]);
            }
    } else if (path == 2) {
        for (int a = 0; a < C1N; a++)
            for (int c = 0; c < C0N; c++) {
                float s = 0.f;
#pragma unroll
                for (int g = 0; g < GK; g++) s += w_vs[(a * C0N + c) * GK + g] * R[g];
#pragma unroll
                for (int m = 0; m < 3; m++) KSTORE(8 + a * 3 + m, c, s * u[m]);
            }
    } else {
        for (int a = 0; a < C1N; a++)
            for (int c = 0; c < C1N; c++) {
                float d0 = 0.f, d1 = 0.f;
#pragma unroll
                for (int g = 0; g < GK; g++) {
                    d0 += w_vv0[(a * C1N + c) * GK + g] * R[g];
                    d1 += w_vv1[(a * C1N + c) * GK + g] * R[g];
                }
#pragma unroll
                for (int i = 0; i < 3; i++)
#pragma unroll
                    for (int j = 0; j < 3; j++) {
                        float val = ((i == j) ? d0 : 0.f)
                                  + 0.7071067811865476f * d1 * cross[i][j];
                        KSTORE(8 + a * 3 + i, 8 + c * 3 + j, val);
                    }
            }
    }
#undef KSTORE
}

// ---------------------------------------------------------------------------
// Kernel 3: bf16 mma.sync split-K implicit GEMM with TMA operand loading.
// grid = (6 = 3 M-tiles x 2 N-tiles, NSPL), block = 512 (16 warps, 4Mx4N).
// Per chunk (tap, 64-ci block): 4 TMA boxes (A hi/lo 3D, B hi/lo 4D) into
// SW128-swizzled smem; 3 bf16 precision passes of ldmatrix+mma.
// ---------------------------------------------------------------------------
__device__ __forceinline__ void issue_chunk(int c, uint32_t sbase, uint32_t mbar,
                                            const void* tAh, const void* tAl,
                                            const void* tBh, const void* tBl,
                                            int och0, int z0) {
    int t   = c / 5;
    int ci0 = (c - t * 5) * 64;
    int dz = t / 25, r2 = t - dz * 25;
    int dy = r2 / 5, dx = r2 - dy * 5;
    mbar_expect_tx(mbar, STAGE_BYTES);
    tma3d(sbase + SOFF_AHI, tAh, ci0, och0, t, mbar);
    tma3d(sbase + SOFF_ALO, tAl, ci0, och0, t, mbar);
    tma4d(sbase + SOFF_BHI, tBh, ci0, dx, dy, z0 + dz, mbar);
    tma4d(sbase + SOFF_BLO, tBl, ci0, dx, dy, z0 + dz, mbar);
}

__global__ void __launch_bounds__(512, 1)
gemm_mma(const __grid_constant__ CUtensorMap tAh,
         const __grid_constant__ CUtensorMap tAl,
         const __grid_constant__ CUtensorMap tBh,
         const __grid_constant__ CUtensorMap tBl) {
    extern __shared__ __align__(1024) char smem[];
    const uint32_t sb = smem_u32(smem);
    const int tid = threadIdx.x;
    const int wid = tid >> 5, lane = tid & 31;

    const int mt = blockIdx.x >> 1;          // 0..2
    const int nt = blockIdx.x & 1;           // 0..1
    const int sp = blockIdx.y;
    const int och0 = mt * 128, z0 = nt * 4;
    const int c0 = (sp * NCHUNK) / NSPL;
    const int c1 = ((sp + 1) * NCHUNK) / NSPL;
    const int n  = c1 - c0;

    const uint32_t mb0 = sb, mb1 = sb + 8;
    const uint32_t st[2] = {sb + HDR, sb + HDR + STAGE_BYTES};

    if (tid == 0) { mbar_init(mb0, 1); mbar_init(mb1, 1); }
    asm volatile("fence.proxy.async.shared::cta;" ::: "memory");
    __syncthreads();

    const int warp_m = wid >> 2, warp_n = wid & 3;
    const int m0 = warp_m * 32, n0 = warp_n * 64;

    // per-lane ldmatrix addressing (unchanged from validated R4 layout)
    const int quad = lane >> 3, r8 = lane & 7;
    const int a_row = (quad & 1) * 8 + r8;
    const int a_sel = quad >> 1;
    const int b_grp = quad >> 1;
    const int b_sel = quad & 1;
    const uint32_t pa0 = (uint32_t)((m0 + a_row) * 128);
    const uint32_t pa1 = (uint32_t)((m0 + 16 + a_row) * 128);
    uint32_t pb[4];
#pragma unroll
    for (int j2 = 0; j2 < 4; j2++)
        pb[j2] = (uint32_t)((n0 + j2 * 16 + b_grp * 8 + r8) * 128);

    float acc[2][8][4];
#pragma unroll
    for (int mi = 0; mi < 2; mi++)
#pragma unroll
        for (int nj = 0; nj < 8; nj++)
#pragma unroll
            for (int e = 0; e < 4; e++) acc[mi][nj][e] = 0.f;

    if (tid == 0) {
        issue_chunk(c0,     st[0], mb0, &tAh, &tAl, &tBh, &tBl, och0, z0);
        issue_chunk(c0 + 1, st[1], mb1, &tAh, &tAl, &tBh, &tBl, och0, z0);
    }

    int ph0 = 0, ph1 = 0;
    for (int i = 0; i < n; i++) {
        const int s = i & 1;
        const uint32_t sbase = st[s];
        const uint32_t mbar = s ? mb1 : mb0;
        if (s) { mbar_wait(mbar, ph1); ph1 ^= 1; }
        else   { mbar_wait(mbar, ph0); ph0 ^= 1; }

        // 3 precision passes: (Ahi,Bhi), (Ahi,Blo), (Alo,Bhi)
#pragma unroll
        for (int ps = 0; ps < 3; ps++) {
            const uint32_t Ab = sbase + (ps == 2 ? SOFF_ALO : SOFF_AHI);
            const uint32_t Bb = sbase + (ps == 1 ? SOFF_BLO : SOFF_BHI);
#pragma unroll
            for (int g = 0; g < 4; g++) {
                const uint32_t aoff = (uint32_t)((((g << 1) + a_sel) ^ r8) << 4);
                const uint32_t boff = (uint32_t)((((g << 1) + b_sel) ^ r8) << 4);
                uint32_t a0[4], a1[4];
                ldm4(a0[0], a0[1], a0[2], a0[3], Ab + pa0 + aoff);
                ldm4(a1[0], a1[1], a1[2], a1[3], Ab + pa1 + aoff);
#pragma unroll
                for (int j2 = 0; j2 < 4; j2++) {
                    uint32_t b[4];
                    ldm4(b[0], b[1], b[2], b[3], Bb + pb[j2] + boff);
                    mma16816(acc[0][2 * j2],     a0[0], a0[1], a0[2], a0[3], b[0], b[1]);
                    mma16816(acc[0][2 * j2 + 1], a0[0], a0[1], a0[2], a0[3], b[2], b[3]);
                    mma16816(acc[1][2 * j2],     a1[0], a1[1], a1[2], a1[3], b[0], b[1]);
                    mma16816(acc[1][2 * j2 + 1], a1[0], a1[1], a1[2], a1[3], b[2], b[3]);
                }
            }
        }
        __syncthreads();
        if (tid == 0 && i + 2 < n)
            issue_chunk(c0 + i + 2, sbase, mbar, &tAh, &tAl, &tBh, &tBl, och0, z0);
    }

    // epilogue -> g_part[sp][blockIdx.x][128][256]
    float* dst = g_part + (size_t)(sp * 6 + blockIdx.x) * (128 * 256);
    const int gidx = lane >> 2, tid4 = lane & 3;
#pragma unroll
    for (int mi = 0; mi < 2; mi++)
#pragma unroll
        for (int nj = 0; nj < 8; nj++) {
            int row = m0 + 16 * mi + gidx;
            int col = n0 + 8 * nj + tid4 * 2;
            *(float2*)(dst + row * 256 + col) =
                make_float2(acc[mi][nj][0], acc[mi][nj][1]);
            *(float2*)(dst + (row + 8) * 256 + col) =
                make_float2(acc[mi][nj][2], acc[mi][nj][3]);
        }
}

// ---------------------------------------------------------------------------
// Kernel 4: reduce split partials + bias.
// ---------------------------------------------------------------------------
__global__ void reduce_kernel(float* __restrict__ out,
                              const float* __restrict__ bias) {
    int i = blockIdx.x * blockDim.x + threadIdx.x;
    if (i >= NCH * VOX) return;
    int och = i >> 9, v = i & 511;
    int m = och >> 7, ro = och & 127;
    int ntl = v >> 8, rv = v & 255;
    int blk = m * 2 + ntl;
    float s = 0.f;
#pragma unroll
    for (int sp = 0; sp < NSPL; sp++)
        s += g_part[(size_t)(sp * 6 + blk) * (128 * 256) + ro * 256 + rv];
    int d = och >> 4;
    if (d < C0N) s += bias[d];
    out[i] = s;
}

// ---------------------------------------------------------------------------
typedef CUresult (*EncodeFn)(CUtensorMap*, CUtensorMapDataType, cuuint32_t, void*,
                             const cuuint64_t*, const cuuint64_t*, const cuuint32_t*,
                             const cuuint32_t*, CUtensorMapInterleave, CUtensorMapSwizzle,
                             CUtensorMapL2promotion, CUtensorMapFloatOOBfill);

static void make_map_3d(EncodeFn enc, CUtensorMap* m, void* base) {
    cuuint64_t dims[3]    = {NCH, NCH, K3T};
    cuuint64_t strides[2] = {NCH * 2ull, (cuuint64_t)NCH * NCH * 2ull};
    cuuint32_t box[3]     = {64, 128, 1};
    cuuint32_t es[3]      = {1, 1, 1};
    enc(m, CU_TENSOR_MAP_DATA_TYPE_BFLOAT16, 3, base, dims, strides, box, es,
        CU_TENSOR_MAP_INTERLEAVE_NONE, CU_TENSOR_MAP_SWIZZLE_128B,
        CU_TENSOR_MAP_L2_PROMOTION_L2_128B, CU_TENSOR_MAP_FLOAT_OOB_FILL_NONE);
}
static void make_map_4d(EncodeFn enc, CUtensorMap* m, void* base) {
    cuuint64_t dims[4]    = {NCH, 12, 12, 12};
    cuuint64_t strides[3] = {NCH * 2ull, NCH * 12 * 2ull, NCH * 144 * 2ull};
    cuuint32_t box[4]     = {64, 8, 8, 4};
    cuuint32_t es[4]      = {1, 1, 1, 1};
    enc(m, CU_TENSOR_MAP_DATA_TYPE_BFLOAT16, 4, base, dims, strides, box, es,
        CU_TENSOR_MAP_INTERLEAVE_NONE, CU_TENSOR_MAP_SWIZZLE_128B,
        CU_TENSOR_MAP_L2_PROMOTION_L2_128B, CU_TENSOR_MAP_FLOAT_OOB_FILL_NONE);
}

extern "C" void kernel_launch(void* const* d_in, const int* in_sizes, int n_in,
                              void* d_out, int out_size) {
    const float* x     = (const float*)d_in[0];
    const float* q_in  = (const float*)d_in[1];
    const float* q_out = (const float*)d_in[2];
    const float* w_ss  = (const float*)d_in[3];
    const float* w_vs  = (const float*)d_in[4];
    const float* w_sv  = (const float*)d_in[5];
    const float* w_vv0 = (const float*)d_in[6];
    const float* w_vv1 = (const float*)d_in[7];
    const float* bias  = (const float*)d_in[8];
    float* out = (float*)d_out;

    // resolve cuTensorMapEncodeTiled without a link-time -lcuda dependency
    void* lib = dlopen("libcuda.so.1", RTLD_LAZY | RTLD_GLOBAL);
    EncodeFn enc = lib ? (EncodeFn)dlsym(lib, "cuTensorMapEncodeTiled") : nullptr;

    void *pAh, *pAl, *pBh, *pBl;
    cudaGetSymbolAddress(&pAh, gA_hi);
    cudaGetSymbolAddress(&pAl, gA_lo);
    cudaGetSymbolAddress(&pBh, gXp_hi);
    cudaGetSymbolAddress(&pBl, gXp_lo);

    CUtensorMap mAh, mAl, mBh, mBl;
    make_map_3d(enc, &mAh, pAh);
    make_map_3d(enc, &mAl, pAl);
    make_map_4d(enc, &mBh, pBh);
    make_map_4d(enc, &mBl, pBl);

    xpad_kernel<<<(1728 * NCH + 255) / 256, 256>>>(x);

    dim3 bgrid((QN * QN * K3T + 255) / 256, 4);
    build_kern_kernel<<<bgrid, 256>>>(q_in, q_out, w_ss, w_vs, w_sv, w_vv0, w_vv1);

    cudaFuncSetAttribute(gemm_mma, cudaFuncAttributeMaxDynamicSharedMemorySize, SMEM_TOTAL);
    gemm_mma<<<dim3(6, NSPL), 512, SMEM_TOTAL>>>(mAh, mAl, mBh, mBl);

    reduce_kernel<<<(NCH * VOX + 255) / 256, 256>>>(out, bias);
}

// round 6
// speedup vs baseline: 3.3225x; 3.3225x over previous
#include <cuda_runtime.h>
#include <cuda.h>
#include <cuda_fp16.h>
#include <math.h>
#include <stdint.h>
#include <dlfcn.h>

// ---------------- problem constants ----------------
#define QN    16
#define C0N   8
#define C1N   4
#define K3T   125
#define NCH   320
#define VOX   512
#define GK    8
#define NSPL  24
#define NCHUNK 625          // 125 taps * 5 ci-blocks of 64
#define NSTG  4             // pipeline stages

// smem stage layout (bytes) after 1KB header
#define SOFF_A 0
#define SOFF_B 16384
#define STAGE_BYTES 49152
#define HDR 1024
#define SMEM_TOTAL (HDR + NSTG * STAGE_BYTES)

// ---------------- device globals ----------------
__device__ __half gA[(size_t)K3T * NCH * NCH];   // [tap][och][ci]
__device__ __half gXp[1728 * NCH];               // [pz*144+py*12+px][ci]
__device__ float g_part[(size_t)NSPL * 6 * 128 * 256];

// ---------------- PTX helpers ----------------
__device__ __forceinline__ uint32_t smem_u32(const void* p) {
    uint32_t a;
    asm("{ .reg .u64 t; cvta.to.shared.u64 t, %1; cvt.u32.u64 %0, t; }" : "=r"(a) : "l"(p));
    return a;
}
__device__ __forceinline__ void ldm4(uint32_t& r0, uint32_t& r1, uint32_t& r2,
                                     uint32_t& r3, uint32_t addr) {
    asm volatile("ldmatrix.sync.aligned.m8n8.x4.shared.b16 {%0,%1,%2,%3}, [%4];"
                 : "=r"(r0), "=r"(r1), "=r"(r2), "=r"(r3) : "r"(addr));
}
__device__ __forceinline__ void mma16816(float* c, uint32_t a0, uint32_t a1,
                                         uint32_t a2, uint32_t a3,
                                         uint32_t b0, uint32_t b1) {
    asm volatile("mma.sync.aligned.m16n8k16.row.col.f32.f16.f16.f32 "
                 "{%0,%1,%2,%3}, {%4,%5,%6,%7}, {%8,%9}, {%0,%1,%2,%3};"
                 : "+f"(c[0]), "+f"(c[1]), "+f"(c[2]), "+f"(c[3])
                 : "r"(a0), "r"(a1), "r"(a2), "r"(a3), "r"(b0), "r"(b1));
}
__device__ __forceinline__ void mbar_init(uint32_t a, uint32_t n) {
    asm volatile("mbarrier.init.shared.b64 [%0], %1;" :: "r"(a), "r"(n) : "memory");
}
__device__ __forceinline__ void mbar_expect_tx(uint32_t a, uint32_t bytes) {
    asm volatile("mbarrier.arrive.expect_tx.shared.b64 _, [%0], %1;"
                 :: "r"(a), "r"(bytes) : "memory");
}
__device__ __forceinline__ void mbar_wait(uint32_t mbar, uint32_t parity) {
    uint32_t done;
    asm volatile("{\n\t.reg .pred p;\n\t"
                 "mbarrier.try_wait.parity.acquire.cta.shared::cta.b64 p, [%1], %2;\n\t"
                 "selp.b32 %0, 1, 0, p;\n\t}"
                 : "=r"(done) : "r"(mbar), "r"(parity) : "memory");
    if (!done) {
        asm volatile("{\n\t.reg .pred P1;\n\t"
                     "W%=:\n\t"
                     "mbarrier.try_wait.parity.acquire.cta.shared::cta.b64 P1, [%0], %1, 0x989680;\n\t"
                     "@P1 bra.uni D%=;\n\t"
                     "bra.uni W%=;\n\t"
                     "D%=:\n\t}"
                     :: "r"(mbar), "r"(parity) : "memory");
    }
}
__device__ __forceinline__ void tma3d(uint32_t dst, const void* map,
                                      int c0, int c1, int c2, uint32_t mbar) {
    asm volatile("cp.async.bulk.tensor.3d.shared::cta.global.tile.mbarrier::complete_tx::bytes "
                 "[%0], [%1, {%2, %3, %4}], [%5];"
                 :: "r"(dst), "l"(map), "r"(c0), "r"(c1), "r"(c2), "r"(mbar) : "memory");
}
__device__ __forceinline__ void tma4d(uint32_t dst, const void* map,
                                      int c0, int c1, int c2, int c3, uint32_t mbar) {
    asm volatile("cp.async.bulk.tensor.4d.shared::cta.global.tile.mbarrier::complete_tx::bytes "
                 "[%0], [%1, {%2, %3, %4, %5}], [%6];"
                 :: "r"(dst), "l"(map), "r"(c0), "r"(c1), "r"(c2), "r"(c3), "r"(mbar) : "memory");
}

// ---------------------------------------------------------------------------
// Kernel 1: x -> transposed + halo-padded fp16 [1728 pos][320 ci]
// ---------------------------------------------------------------------------
__global__ void xpad_kernel(const float* __restrict__ x) {
    int i = blockIdx.x * blockDim.x + threadIdx.x;
    if (i >= 1728 * NCH) return;
    int ci = i % NCH, ppos = i / NCH;
    int px = ppos % 12, py = (ppos / 12) % 12, pz = ppos / 144;
    int z = pz - 2, y = py - 2, xx = px - 2;
    float v = 0.f;
    if ((unsigned)z < 8 && (unsigned)y < 8 && (unsigned)xx < 8)
        v = x[ci * VOX + z * 64 + y * 8 + xx];
    gXp[i] = __float2half(v);
}

// ---------------------------------------------------------------------------
// Kernel 2: build equivariant kernel -> gA [tap][och][ci] fp16.
// ---------------------------------------------------------------------------
__global__ void build_kern_kernel(const float* __restrict__ q_in,
                                  const float* __restrict__ q_out,
                                  const float* __restrict__ w_ss,
                                  const float* __restrict__ w_vs,
                                  const float* __restrict__ w_sv,
                                  const float* __restrict__ w_vv0,
                                  const float* __restrict__ w_vv1) {
    int idx = blockIdx.x * blockDim.x + threadIdx.x;
    if (idx >= QN * QN * K3T) return;
    int t = idx % K3T;
    int q = (idx / K3T) % QN;
    int p = idx / (K3T * QN);
    int path = blockIdx.y;

    int dz = t / 25, dy = (t / 5) % 5, dx = t % 5;
    float v0 = (float)(dz - 2) - (q_out[p * 3 + 0] - q_in[q * 3 + 0]);
    float v1 = (float)(dy - 2) - (q_out[p * 3 + 1] - q_in[q * 3 + 1]);
    float v2 = (float)(dx - 2) - (q_out[p * 3 + 2] - q_in[q * 3 + 2]);
    float r  = sqrtf(v0 * v0 + v1 * v1 + v2 * v2);
    float inv = (r > 1e-6f) ? (1.0f / r) : 0.0f;
    float u[3] = {v0 * inv, v1 * inv, v2 * inv};

    const float sigma = 5.5f / 7.0f;
    float R[GK];
#pragma unroll
    for (int g = 0; g < GK; g++) {
        float d = (r - sigma * (float)g) / sigma;
        R[g] = expf(-0.5f * d * d);
    }

    float cross[3][3];
    cross[0][0] = 0.f;    cross[0][1] = -u[2];  cross[0][2] =  u[1];
    cross[1][0] =  u[2];  cross[1][1] = 0.f;    cross[1][2] = -u[0];
    cross[2][0] = -u[1];  cross[2][1] =  u[0];  cross[2][2] = 0.f;

#define KSTORE(row, col, val) \
    gA[((size_t)t * NCH + ((row) * QN + p)) * NCH + ((col) * QN + q)] = __float2half(val)

    if (path == 0) {
        for (int a = 0; a < C0N; a++)
            for (int c = 0; c < C0N; c++) {
                float s = 0.f;
#pragma unroll
                for (int g = 0; g < GK; g++) s += w_ss[(a * C0N + c) * GK + g] * R[g];
                KSTORE(a, c, s);
            }
    } else if (path == 1) {
        for (int a = 0; a < C0N; a++)
            for (int c = 0; c < C1N; c++) {
                float s = 0.f;
#pragma unroll
                for (int g = 0; g < GK; g++) s += w_sv[(a * C1N + c) * GK + g] * R[g];
#pragma unroll
                for (int j = 0; j < 3; j++) KSTORE(a, 8 + c * 3 + j, s * u[j]);
            }
    } else if (path == 2) {
        for (int a = 0; a < C1N; a++)
            for (int c = 0; c < C0N; c++) {
                float s = 0.f;
#pragma unroll
                for (int g = 0; g < GK; g++) s += w_vs[(a * C0N + c) * GK + g] * R[g];
#pragma unroll
                for (int m = 0; m < 3; m++) KSTORE(8 + a * 3 + m, c, s * u[m]);
            }
    } else {
        for (int a = 0; a < C1N; a++)
            for (int c = 0; c < C1N; c++) {
                float d0 = 0.f, d1 = 0.f;
#pragma unroll
                for (int g = 0; g < GK; g++) {
                    d0 += w_vv0[(a * C1N + c) * GK + g] * R[g];
                    d1 += w_vv1[(a * C1N + c) * GK + g] * R[g];
                }
#pragma unroll
                for (int i = 0; i < 3; i++)
#pragma unroll
                    for (int j = 0; j < 3; j++) {
                        float val = ((i == j) ? d0 : 0.f)
                                  + 0.7071067811865476f * d1 * cross[i][j];
                        KSTORE(8 + a * 3 + i, 8 + c * 3 + j, val);
                    }
            }
    }
#undef KSTORE
}

// ---------------------------------------------------------------------------
// Kernel 3: fp16 single-pass mma.sync split-K implicit GEMM, 4-stage TMA pipe.
// grid = (6 = 3 M-tiles x 2 N-tiles, NSPL), block = 512 (16 warps, 4Mx4N).
// ---------------------------------------------------------------------------
__device__ __forceinline__ void issue_chunk(int c, uint32_t sbase, uint32_t mbar,
                                            const void* tA, const void* tB,
                                            int och0, int z0) {
    int t   = c / 5;
    int ci0 = (c - t * 5) * 64;
    int dz = t / 25, r2 = t - dz * 25;
    int dy = r2 / 5, dx = r2 - dy * 5;
    mbar_expect_tx(mbar, STAGE_BYTES);
    tma3d(sbase + SOFF_A, tA, ci0, och0, t, mbar);
    tma4d(sbase + SOFF_B, tB, ci0, dx, dy, z0 + dz, mbar);
}

__global__ void __launch_bounds__(512, 1)
gemm_mma(const __grid_constant__ CUtensorMap tA,
         const __grid_constant__ CUtensorMap tB) {
    extern __shared__ __align__(1024) char smem[];
    const uint32_t sb = smem_u32(smem);
    const int tid = threadIdx.x;
    const int wid = tid >> 5, lane = tid & 31;

    const int mt = blockIdx.x >> 1;
    const int nt = blockIdx.x & 1;
    const int sp = blockIdx.y;
    const int och0 = mt * 128, z0 = nt * 4;
    const int c0 = (sp * NCHUNK) / NSPL;
    const int c1 = ((sp + 1) * NCHUNK) / NSPL;
    const int n  = c1 - c0;

    const uint32_t st0 = sb + HDR;

    if (tid == 0)
        for (int s = 0; s < NSTG; s++) mbar_init(sb + 8 * s, 1);
    asm volatile("fence.proxy.async.shared::cta;" ::: "memory");
    __syncthreads();

    const int warp_m = wid >> 2, warp_n = wid & 3;
    const int m0 = warp_m * 32, n0 = warp_n * 64;

    const int quad = lane >> 3, r8 = lane & 7;
    const int a_row = (quad & 1) * 8 + r8;
    const int a_sel = quad >> 1;
    const int b_grp = quad >> 1;
    const int b_sel = quad & 1;
    const uint32_t pa0 = (uint32_t)((m0 + a_row) * 128);
    const uint32_t pa1 = (uint32_t)((m0 + 16 + a_row) * 128);
    uint32_t pb[4];
#pragma unroll
    for (int j2 = 0; j2 < 4; j2++)
        pb[j2] = (uint32_t)((n0 + j2 * 16 + b_grp * 8 + r8) * 128);

    float acc[2][8][4];
#pragma unroll
    for (int mi = 0; mi < 2; mi++)
#pragma unroll
        for (int nj = 0; nj < 8; nj++)
#pragma unroll
            for (int e = 0; e < 4; e++) acc[mi][nj][e] = 0.f;

    if (tid == 0)
        for (int i = 0; i < NSTG - 1 && i < n; i++)
            issue_chunk(c0 + i, st0 + (uint32_t)i * STAGE_BYTES, sb + 8 * i,
                        &tA, &tB, och0, z0);

    for (int i = 0; i < n; i++) {
        const int s = i & (NSTG - 1);
        const uint32_t sbase = st0 + (uint32_t)s * STAGE_BYTES;
        mbar_wait(sb + 8 * s, (i >> 2) & 1);

#pragma unroll
        for (int g = 0; g < 4; g++) {
            const uint32_t aoff = (uint32_t)((((g << 1) + a_sel) ^ r8) << 4);
            const uint32_t boff = (uint32_t)((((g << 1) + b_sel) ^ r8) << 4);
            uint32_t a0[4], a1[4];
            ldm4(a0[0], a0[1], a0[2], a0[3], sbase + SOFF_A + pa0 + aoff);
            ldm4(a1[0], a1[1], a1[2], a1[3], sbase + SOFF_A + pa1 + aoff);
#pragma unroll
            for (int j2 = 0; j2 < 4; j2++) {
                uint32_t b[4];
                ldm4(b[0], b[1], b[2], b[3], sbase + SOFF_B + pb[j2] + boff);
                mma16816(acc[0][2 * j2],     a0[0], a0[1], a0[2], a0[3], b[0], b[1]);
                mma16816(acc[0][2 * j2 + 1], a0[0], a0[1], a0[2], a0[3], b[2], b[3]);
                mma16816(acc[1][2 * j2],     a1[0], a1[1], a1[2], a1[3], b[0], b[1]);
                mma16816(acc[1][2 * j2 + 1], a1[0], a1[1], a1[2], a1[3], b[2], b[3]);
            }
        }
        __syncthreads();
        if (tid == 0 && i + NSTG - 1 < n)
            issue_chunk(c0 + i + NSTG - 1, st0 + (uint32_t)((i + NSTG - 1) & (NSTG - 1)) * STAGE_BYTES,
                        sb + 8 * ((i + NSTG - 1) & (NSTG - 1)), &tA, &tB, och0, z0);
    }

    float* dst = g_part + (size_t)(sp * 6 + blockIdx.x) * (128 * 256);
    const int gidx = lane >> 2, tid4 = lane & 3;
#pragma unroll
    for (int mi = 0; mi < 2; mi++)
#pragma unroll
        for (int nj = 0; nj < 8; nj++) {
            int row = m0 + 16 * mi + gidx;
            int col = n0 + 8 * nj + tid4 * 2;
            *(float2*)(dst + row * 256 + col) =
                make_float2(acc[mi][nj][0], acc[mi][nj][1]);
            *(float2*)(dst + (row + 8) * 256 + col) =
                make_float2(acc[mi][nj][2], acc[mi][nj][3]);
        }
}

// ---------------------------------------------------------------------------
// Kernel 4: reduce split partials + bias.
// ---------------------------------------------------------------------------
__global__ void reduce_kernel(float* __restrict__ out,
                              const float* __restrict__ bias) {
    int i = blockIdx.x * blockDim.x + threadIdx.x;
    if (i >= NCH * VOX) return;
    int och = i >> 9, v = i & 511;
    int m = och >> 7, ro = och & 127;
    int ntl = v >> 8, rv = v & 255;
    int blk = m * 2 + ntl;
    float s = 0.f;
#pragma unroll
    for (int sp = 0; sp < NSPL; sp++)
        s += g_part[(size_t)(sp * 6 + blk) * (128 * 256) + ro * 256 + rv];
    int d = och >> 4;
    if (d < C0N) s += bias[d];
    out[i] = s;
}

// ---------------------------------------------------------------------------
typedef CUresult (*EncodeFn)(CUtensorMap*, CUtensorMapDataType, cuuint32_t, void*,
                             const cuuint64_t*, const cuuint64_t*, const cuuint32_t*,
                             const cuuint32_t*, CUtensorMapInterleave, CUtensorMapSwizzle,
                             CUtensorMapL2promotion, CUtensorMapFloatOOBfill);

static void make_map_3d(EncodeFn enc, CUtensorMap* m, void* base) {
    cuuint64_t dims[3]    = {NCH, NCH, K3T};
    cuuint64_t strides[2] = {NCH * 2ull, (cuuint64_t)NCH * NCH * 2ull};
    cuuint32_t box[3]     = {64, 128, 1};
    cuuint32_t es[3]      = {1, 1, 1};
    enc(m, CU_TENSOR_MAP_DATA_TYPE_FLOAT16, 3, base, dims, strides, box, es,
        CU_TENSOR_MAP_INTERLEAVE_NONE, CU_TENSOR_MAP_SWIZZLE_128B,
        CU_TENSOR_MAP_L2_PROMOTION_L2_128B, CU_TENSOR_MAP_FLOAT_OOB_FILL_NONE);
}
static void make_map_4d(EncodeFn enc, CUtensorMap* m, void* base) {
    cuuint64_t dims[4]    = {NCH, 12, 12, 12};
    cuuint64_t strides[3] = {NCH * 2ull, NCH * 12 * 2ull, NCH * 144 * 2ull};
    cuuint32_t box[4]     = {64, 8, 8, 4};
    cuuint32_t es[4]      = {1, 1, 1, 1};
    enc(m, CU_TENSOR_MAP_DATA_TYPE_FLOAT16, 4, base, dims, strides, box, es,
        CU_TENSOR_MAP_INTERLEAVE_NONE, CU_TENSOR_MAP_SWIZZLE_128B,
        CU_TENSOR_MAP_L2_PROMOTION_L2_128B, CU_TENSOR_MAP_FLOAT_OOB_FILL_NONE);
}

extern "C" void kernel_launch(void* const* d_in, const int* in_sizes, int n_in,
                              void* d_out, int out_size) {
    const float* x     = (const float*)d_in[0];
    const float* q_in  = (const float*)d_in[1];
    const float* q_out = (const float*)d_in[2];
    const float* w_ss  = (const float*)d_in[3];
    const float* w_vs  = (const float*)d_in[4];
    const float* w_sv  = (const float*)d_in[5];
    const float* w_vv0 = (const float*)d_in[6];
    const float* w_vv1 = (const float*)d_in[7];
    const float* bias  = (const float*)d_in[8];
    float* out = (float*)d_out;

    void* lib = dlopen("libcuda.so.1", RTLD_LAZY | RTLD_GLOBAL);
    EncodeFn enc = lib ? (EncodeFn)dlsym(lib, "cuTensorMapEncodeTiled") : nullptr;

    void *pA, *pB;
    cudaGetSymbolAddress(&pA, gA);
    cudaGetSymbolAddress(&pB, gXp);

    CUtensorMap mA, mB;
    make_map_3d(enc, &mA, pA);
    make_map_4d(enc, &mB, pB);

    xpad_kernel<<<(1728 * NCH + 255) / 256, 256>>>(x);

    dim3 bgrid((QN * QN * K3T + 255) / 256, 4);
    build_kern_kernel<<<bgrid, 256>>>(q_in, q_out, w_ss, w_vs, w_sv, w_vv0, w_vv1);

    cudaFuncSetAttribute(gemm_mma, cudaFuncAttributeMaxDynamicSharedMemorySize, SMEM_TOTAL);
    gemm_mma<<<dim3(6, NSPL), 512, SMEM_TOTAL>>>(mA, mB);

    reduce_kernel<<<(NCH * VOX + 255) / 256, 256>>>(out, bias);
}

// round 7
// speedup vs baseline: 3.5246x; 1.0608x over previous
#include <cuda_runtime.h>
#include <cuda.h>
#include <cuda_fp16.h>
#include <math.h>
#include <stdint.h>
#include <dlfcn.h>

// ---------------- problem constants ----------------
#define QN    16
#define C0N   8
#define C1N   4
#define K3T   125
#define NCH   320
#define VOX   512
#define GK    8
#define NSPL  29
#define NCHUNK 625          // 125 taps * 5 ci-blocks of 64
#define NSTG  2             // double buffer

// smem stage layout (bytes) after 1KB header
#define SOFF_A 0
#define SOFF_B 8192
#define STAGE_BYTES 40960
#define HDR 1024
#define SMEM_TOTAL (HDR + NSTG * STAGE_BYTES)

// ---------------- device globals ----------------
__device__ __half gA[(size_t)K3T * NCH * NCH];   // [tap][och][ci]
__device__ __half gXp[1728 * NCH];               // [pz*144+py*12+px][ci]
__device__ float g_part[(size_t)NSPL * 10 * 64 * 256];

// ---------------- PTX helpers ----------------
__device__ __forceinline__ uint32_t smem_u32(const void* p) {
    uint32_t a;
    asm("{ .reg .u64 t; cvta.to.shared.u64 t, %1; cvt.u32.u64 %0, t; }" : "=r"(a) : "l"(p));
    return a;
}
__device__ __forceinline__ void ldm4(uint32_t& r0, uint32_t& r1, uint32_t& r2,
                                     uint32_t& r3, uint32_t addr) {
    asm volatile("ldmatrix.sync.aligned.m8n8.x4.shared.b16 {%0,%1,%2,%3}, [%4];"
                 : "=r"(r0), "=r"(r1), "=r"(r2), "=r"(r3) : "r"(addr));
}
__device__ __forceinline__ void mma16816(float* c, uint32_t a0, uint32_t a1,
                                         uint32_t a2, uint32_t a3,
                                         uint32_t b0, uint32_t b1) {
    asm volatile("mma.sync.aligned.m16n8k16.row.col.f32.f16.f16.f32 "
                 "{%0,%1,%2,%3}, {%4,%5,%6,%7}, {%8,%9}, {%0,%1,%2,%3};"
                 : "+f"(c[0]), "+f"(c[1]), "+f"(c[2]), "+f"(c[3])
                 : "r"(a0), "r"(a1), "r"(a2), "r"(a3), "r"(b0), "r"(b1));
}
__device__ __forceinline__ void mbar_init(uint32_t a, uint32_t n) {
    asm volatile("mbarrier.init.shared.b64 [%0], %1;" :: "r"(a), "r"(n) : "memory");
}
__device__ __forceinline__ void mbar_expect_tx(uint32_t a, uint32_t bytes) {
    asm volatile("mbarrier.arrive.expect_tx.shared.b64 _, [%0], %1;"
                 :: "r"(a), "r"(bytes) : "memory");
}
__device__ __forceinline__ void mbar_wait(uint32_t mbar, uint32_t parity) {
    uint32_t done;
    asm volatile("{\n\t.reg .pred p;\n\t"
                 "mbarrier.try_wait.parity.acquire.cta.shared::cta.b64 p, [%1], %2;\n\t"
                 "selp.b32 %0, 1, 0, p;\n\t}"
                 : "=r"(done) : "r"(mbar), "r"(parity) : "memory");
    if (!done) {
        asm volatile("{\n\t.reg .pred P1;\n\t"
                     "W%=:\n\t"
                     "mbarrier.try_wait.parity.acquire.cta.shared::cta.b64 P1, [%0], %1, 0x989680;\n\t"
                     "@P1 bra.uni D%=;\n\t"
                     "bra.uni W%=;\n\t"
                     "D%=:\n\t}"
                     :: "r"(mbar), "r"(parity) : "memory");
    }
}
__device__ __forceinline__ void tma3d(uint32_t dst, const void* map,
                                      int c0, int c1, int c2, uint32_t mbar) {
    asm volatile("cp.async.bulk.tensor.3d.shared::cta.global.tile.mbarrier::complete_tx::bytes "
                 "[%0], [%1, {%2, %3, %4}], [%5];"
                 :: "r"(dst), "l"(map), "r"(c0), "r"(c1), "r"(c2), "r"(mbar) : "memory");
}
__device__ __forceinline__ void tma4d(uint32_t dst, const void* map,
                                      int c0, int c1, int c2, int c3, uint32_t mbar) {
    asm volatile("cp.async.bulk.tensor.4d.shared::cta.global.tile.mbarrier::complete_tx::bytes "
                 "[%0], [%1, {%2, %3, %4, %5}], [%6];"
                 :: "r"(dst), "l"(map), "r"(c0), "r"(c1), "r"(c2), "r"(c3), "r"(mbar) : "memory");
}

// ---------------------------------------------------------------------------
// Kernel 1: x -> transposed + halo-padded fp16 [1728 pos][320 ci]
// ---------------------------------------------------------------------------
__global__ void xpad_kernel(const float* __restrict__ x) {
    int i = blockIdx.x * blockDim.x + threadIdx.x;
    if (i >= 1728 * NCH) return;
    int ci = i % NCH, ppos = i / NCH;
    int px = ppos % 12, py = (ppos / 12) % 12, pz = ppos / 144;
    int z = pz - 2, y = py - 2, xx = px - 2;
    float v = 0.f;
    if ((unsigned)z < 8 && (unsigned)y < 8 && (unsigned)xx < 8)
        v = x[ci * VOX + z * 64 + y * 8 + xx];
    gXp[i] = __float2half(v);
}

// ---------------------------------------------------------------------------
// Kernel 2: build equivariant kernel -> gA [tap][och][ci] fp16.
// ---------------------------------------------------------------------------
__global__ void build_kern_kernel(const float* __restrict__ q_in,
                                  const float* __restrict__ q_out,
                                  const float* __restrict__ w_ss,
                                  const float* __restrict__ w_vs,
                                  const float* __restrict__ w_sv,
                                  const float* __restrict__ w_vv0,
                                  const float* __restrict__ w_vv1) {
    int idx = blockIdx.x * blockDim.x + threadIdx.x;
    if (idx >= QN * QN * K3T) return;
    int t = idx % K3T;
    int q = (idx / K3T) % QN;
    int p = idx / (K3T * QN);
    int path = blockIdx.y;

    int dz = t / 25, dy = (t / 5) % 5, dx = t % 5;
    float v0 = (float)(dz - 2) - (q_out[p * 3 + 0] - q_in[q * 3 + 0]);
    float v1 = (float)(dy - 2) - (q_out[p * 3 + 1] - q_in[q * 3 + 1]);
    float v2 = (float)(dx - 2) - (q_out[p * 3 + 2] - q_in[q * 3 + 2]);
    float r  = sqrtf(v0 * v0 + v1 * v1 + v2 * v2);
    float inv = (r > 1e-6f) ? (1.0f / r) : 0.0f;
    float u[3] = {v0 * inv, v1 * inv, v2 * inv};

    const float sigma = 5.5f / 7.0f;
    float R[GK];
#pragma unroll
    for (int g = 0; g < GK; g++) {
        float d = (r - sigma * (float)g) / sigma;
        R[g] = expf(-0.5f * d * d);
    }

    float cross[3][3];
    cross[0][0] = 0.f;    cross[0][1] = -u[2];  cross[0][2] =  u[1];
    cross[1][0] =  u[2];  cross[1][1] = 0.f;    cross[1][2] = -u[0];
    cross[2][0] = -u[1];  cross[2][1] =  u[0];  cross[2][2] = 0.f;

#define KSTORE(row, col, val) \
    gA[((size_t)t * NCH + ((row) * QN + p)) * NCH + ((col) * QN + q)] = __float2half(val)

    if (path == 0) {
        for (int a = 0; a < C0N; a++)
            for (int c = 0; c < C0N; c++) {
                float s = 0.f;
#pragma unroll
                for (int g = 0; g < GK; g++) s += w_ss[(a * C0N + c) * GK + g] * R[g];
                KSTORE(a, c, s);
            }
    } else if (path == 1) {
        for (int a = 0; a < C0N; a++)
            for (int c = 0; c < C1N; c++) {
                float s = 0.f;
#pragma unroll
                for (int g = 0; g < GK; g++) s += w_sv[(a * C1N + c) * GK + g] * R[g];
#pragma unroll
                for (int j = 0; j < 3; j++) KSTORE(a, 8 + c * 3 + j, s * u[j]);
            }
    } else if (path == 2) {
        for (int a = 0; a < C1N; a++)
            for (int c = 0; c < C0N; c++) {
                float s = 0.f;
#pragma unroll
                for (int g = 0; g < GK; g++) s += w_vs[(a * C0N + c) * GK + g] * R[g];
#pragma unroll
                for (int m = 0; m < 3; m++) KSTORE(8 + a * 3 + m, c, s * u[m]);
            }
    } else {
        for (int a = 0; a < C1N; a++)
            for (int c = 0; c < C1N; c++) {
                float d0 = 0.f, d1 = 0.f;
#pragma unroll
                for (int g = 0; g < GK; g++) {
                    d0 += w_vv0[(a * C1N + c) * GK + g] * R[g];
                    d1 += w_vv1[(a * C1N + c) * GK + g] * R[g];
                }
#pragma unroll
                for (int i = 0; i < 3; i++)
#pragma unroll
                    for (int j = 0; j < 3; j++) {
                        float val = ((i == j) ? d0 : 0.f)
                                  + 0.7071067811865476f * d1 * cross[i][j];
                        KSTORE(8 + a * 3 + i, 8 + c * 3 + j, val);
                    }
            }
    }
#undef KSTORE
}

// ---------------------------------------------------------------------------
// Kernel 3: fp16 mma.sync split-K implicit GEMM, M64 tiles (no padding),
// 2 CTAs/SM, double-buffered TMA.
// grid = (10 = 5 M-tiles x 2 N-tiles, NSPL), block = 256 (8 warps, 2Mx4N).
// ---------------------------------------------------------------------------
__device__ __forceinline__ void issue_chunk(int c, uint32_t sbase, uint32_t mbar,
                                            const void* tA, const void* tB,
                                            int och0, int z0) {
    int t   = c / 5;
    int ci0 = (c - t * 5) * 64;
    int dz = t / 25, r2 = t - dz * 25;
    int dy = r2 / 5, dx = r2 - dy * 5;
    mbar_expect_tx(mbar, STAGE_BYTES);
    tma3d(sbase + SOFF_A, tA, ci0, och0, t, mbar);
    tma4d(sbase + SOFF_B, tB, ci0, dx, dy, z0 + dz, mbar);
}

__global__ void __launch_bounds__(256, 2)
gemm_mma(const __grid_constant__ CUtensorMap tA,
         const __grid_constant__ CUtensorMap tB) {
    extern __shared__ __align__(1024) char smem[];
    const uint32_t sb = smem_u32(smem);
    const int tid = threadIdx.x;
    const int wid = tid >> 5, lane = tid & 31;

    const int mt = blockIdx.x >> 1;          // 0..4
    const int nt = blockIdx.x & 1;           // 0..1
    const int sp = blockIdx.y;
    const int och0 = mt * 64, z0 = nt * 4;
    const int c0 = (sp * NCHUNK) / NSPL;
    const int c1 = ((sp + 1) * NCHUNK) / NSPL;
    const int n  = c1 - c0;

    const uint32_t st0 = sb + HDR;

    if (tid == 0)
        for (int s = 0; s < NSTG; s++) mbar_init(sb + 8 * s, 1);
    asm volatile("fence.proxy.async.shared::cta;" ::: "memory");
    __syncthreads();

    const int warp_m = wid >> 2, warp_n = wid & 3;   // 2M x 4N
    const int m0 = warp_m * 32, n0 = warp_n * 64;

    const int quad = lane >> 3, r8 = lane & 7;
    const int a_row = (quad & 1) * 8 + r8;
    const int a_sel = quad >> 1;
    const int b_grp = quad >> 1;
    const int b_sel = quad & 1;
    const uint32_t pa0 = (uint32_t)((m0 + a_row) * 128);
    const uint32_t pa1 = (uint32_t)((m0 + 16 + a_row) * 128);
    uint32_t pb[4];
#pragma unroll
    for (int j2 = 0; j2 < 4; j2++)
        pb[j2] = (uint32_t)((n0 + j2 * 16 + b_grp * 8 + r8) * 128);

    float acc[2][8][4];
#pragma unroll
    for (int mi = 0; mi < 2; mi++)
#pragma unroll
        for (int nj = 0; nj < 8; nj++)
#pragma unroll
            for (int e = 0; e < 4; e++) acc[mi][nj][e] = 0.f;

    if (tid == 0) {
        issue_chunk(c0, st0, sb, &tA, &tB, och0, z0);
        if (n > 1) issue_chunk(c0 + 1, st0 + STAGE_BYTES, sb + 8, &tA, &tB, och0, z0);
    }

    for (int i = 0; i < n; i++) {
        const int s = i & 1;
        const uint32_t sbase = st0 + (uint32_t)s * STAGE_BYTES;
        mbar_wait(sb + 8 * s, (i >> 1) & 1);

#pragma unroll
        for (int g = 0; g < 4; g++) {
            const uint32_t aoff = (uint32_t)((((g << 1) + a_sel) ^ r8) << 4);
            const uint32_t boff = (uint32_t)((((g << 1) + b_sel) ^ r8) << 4);
            uint32_t a0[4], a1[4];
            ldm4(a0[0], a0[1], a0[2], a0[3], sbase + SOFF_A + pa0 + aoff);
            ldm4(a1[0], a1[1], a1[2], a1[3], sbase + SOFF_A + pa1 + aoff);
#pragma unroll
            for (int j2 = 0; j2 < 4; j2++) {
                uint32_t b[4];
                ldm4(b[0], b[1], b[2], b[3], sbase + SOFF_B + pb[j2] + boff);
                mma16816(acc[0][2 * j2],     a0[0], a0[1], a0[2], a0[3], b[0], b[1]);
                mma16816(acc[0][2 * j2 + 1], a0[0], a0[1], a0[2], a0[3], b[2], b[3]);
                mma16816(acc[1][2 * j2],     a1[0], a1[1], a1[2], a1[3], b[0], b[1]);
                mma16816(acc[1][2 * j2 + 1], a1[0], a1[1], a1[2], a1[3], b[2], b[3]);
            }
        }
        __syncthreads();
        if (tid == 0 && i + NSTG < n)
            issue_chunk(c0 + i + NSTG, sbase, sb + 8 * s, &tA, &tB, och0, z0);
    }

    // epilogue -> g_part[sp][blockIdx.x][64][256]
    float* dst = g_part + (size_t)(sp * 10 + blockIdx.x) * (64 * 256);
    const int gidx = lane >> 2, tid4 = lane & 3;
#pragma unroll
    for (int mi = 0; mi < 2; mi++)
#pragma unroll
        for (int nj = 0; nj < 8; nj++) {
            int row = m0 + 16 * mi + gidx;
            int col = n0 + 8 * nj + tid4 * 2;
            *(float2*)(dst + row * 256 + col) =
                make_float2(acc[mi][nj][0], acc[mi][nj][1]);
            *(float2*)(dst + (row + 8) * 256 + col) =
                make_float2(acc[mi][nj][2], acc[mi][nj][3]);
        }
}

// ---------------------------------------------------------------------------
// Kernel 4: reduce split partials + bias.
// ---------------------------------------------------------------------------
__global__ void reduce_kernel(float* __restrict__ out,
                              const float* __restrict__ bias) {
    int i = blockIdx.x * blockDim.x + threadIdx.x;
    if (i >= NCH * VOX) return;
    int och = i >> 9, v = i & 511;
    int mt = och >> 6, ro = och & 63;
    int ntl = v >> 8, rv = v & 255;
    int blk = mt * 2 + ntl;
    float s = 0.f;
#pragma unroll
    for (int sp = 0; sp < NSPL; sp++)
        s += g_part[(size_t)(sp * 10 + blk) * (64 * 256) + ro * 256 + rv];
    int d = och >> 4;
    if (d < C0N) s += bias[d];
    out[i] = s;
}

// ---------------------------------------------------------------------------
typedef CUresult (*EncodeFn)(CUtensorMap*, CUtensorMapDataType, cuuint32_t, void*,
                             const cuuint64_t*, const cuuint64_t*, const cuuint32_t*,
                             const cuuint32_t*, CUtensorMapInterleave, CUtensorMapSwizzle,
                             CUtensorMapL2promotion, CUtensorMapFloatOOBfill);

static void make_map_3d(EncodeFn enc, CUtensorMap* m, void* base) {
    cuuint64_t dims[3]    = {NCH, NCH, K3T};
    cuuint64_t strides[2] = {NCH * 2ull, (cuuint64_t)NCH * NCH * 2ull};
    cuuint32_t box[3]     = {64, 64, 1};
    cuuint32_t es[3]      = {1, 1, 1};
    enc(m, CU_TENSOR_MAP_DATA_TYPE_FLOAT16, 3, base, dims, strides, box, es,
        CU_TENSOR_MAP_INTERLEAVE_NONE, CU_TENSOR_MAP_SWIZZLE_128B,
        CU_TENSOR_MAP_L2_PROMOTION_L2_128B, CU_TENSOR_MAP_FLOAT_OOB_FILL_NONE);
}
static void make_map_4d(EncodeFn enc, CUtensorMap* m, void* base) {
    cuuint64_t dims[4]    = {NCH, 12, 12, 12};
    cuuint64_t strides[3] = {NCH * 2ull, NCH * 12 * 2ull, NCH * 144 * 2ull};
    cuuint32_t box[4]     = {64, 8, 8, 4};
    cuuint32_t es[4]      = {1, 1, 1, 1};
    enc(m, CU_TENSOR_MAP_DATA_TYPE_FLOAT16, 4, base, dims, strides, box, es,
        CU_TENSOR_MAP_INTERLEAVE_NONE, CU_TENSOR_MAP_SWIZZLE_128B,
        CU_TENSOR_MAP_L2_PROMOTION_L2_128B, CU_TENSOR_MAP_FLOAT_OOB_FILL_NONE);
}

extern "C" void kernel_launch(void* const* d_in, const int* in_sizes, int n_in,
                              void* d_out, int out_size) {
    const float* x     = (const float*)d_in[0];
    const float* q_in  = (const float*)d_in[1];
    const float* q_out = (const float*)d_in[2];
    const float* w_ss  = (const float*)d_in[3];
    const float* w_vs  = (const float*)d_in[4];
    const float* w_sv  = (const float*)d_in[5];
    const float* w_vv0 = (const float*)d_in[6];
    const float* w_vv1 = (const float*)d_in[7];
    const float* bias  = (const float*)d_in[8];
    float* out = (float*)d_out;

    void* lib = dlopen("libcuda.so.1", RTLD_LAZY | RTLD_GLOBAL);
    EncodeFn enc = lib ? (EncodeFn)dlsym(lib, "cuTensorMapEncodeTiled") : nullptr;

    void *pA, *pB;
    cudaGetSymbolAddress(&pA, gA);
    cudaGetSymbolAddress(&pB, gXp);

    CUtensorMap mA, mB;
    make_map_3d(enc, &mA, pA);
    make_map_4d(enc, &mB, pB);

    xpad_kernel<<<(1728 * NCH + 255) / 256, 256>>>(x);

    dim3 bgrid((QN * QN * K3T + 255) / 256, 4);
    build_kern_kernel<<<bgrid, 256>>>(q_in, q_out, w_ss, w_vs, w_sv, w_vv0, w_vv1);

    cudaFuncSetAttribute(gemm_mma, cudaFuncAttributeMaxDynamicSharedMemorySize, SMEM_TOTAL);
    gemm_mma<<<dim3(10, NSPL), 256, SMEM_TOTAL>>>(mA, mB);

    reduce_kernel<<<(NCH * VOX + 255) / 256, 256>>>(out, bias);
}

// round 11
// speedup vs baseline: 3.5809x; 1.0160x over previous
#include <cuda_runtime.h>
#include <cuda.h>
#include <cuda_fp16.h>
#include <math.h>
#include <stdint.h>
#include <dlfcn.h>

// ---------------- problem constants ----------------
#define QN    16
#define C0N   8
#define C1N   4
#define K3T   125
#define NCH   320
#define VOX   512
#define GK    8
#define NSPL  29
#define NCHUNK 625          // 125 taps * 5 ci-blocks of 64
#define NSTG  2             // double buffer

// smem stage layout (bytes) after 1KB header
#define SOFF_A 0
#define SOFF_B 8192
#define STAGE_BYTES 40960
#define HDR 1024
#define SMEM_TOTAL (HDR + NSTG * STAGE_BYTES)

// ---------------- device globals ----------------
__device__ __half gA[(size_t)K3T * NCH * NCH];   // [tap][och][ci]
__device__ __half gXp[1728 * NCH];               // [pz*144+py*12+px][ci]
__device__ float g_part[(size_t)NSPL * 10 * 64 * 256];

// ---------------- PTX helpers ----------------
__device__ __forceinline__ uint32_t smem_u32(const void* p) {
    uint32_t a;
    asm("{ .reg .u64 t; cvta.to.shared.u64 t, %1; cvt.u32.u64 %0, t; }" : "=r"(a) : "l"(p));
    return a;
}
__device__ __forceinline__ void ldm4(uint32_t& r0, uint32_t& r1, uint32_t& r2,
                                     uint32_t& r3, uint32_t addr) {
    asm volatile("ldmatrix.sync.aligned.m8n8.x4.shared.b16 {%0,%1,%2,%3}, [%4];"
                 : "=r"(r0), "=r"(r1), "=r"(r2), "=r"(r3) : "r"(addr));
}
__device__ __forceinline__ void mma16816(float* c, uint32_t a0, uint32_t a1,
                                         uint32_t a2, uint32_t a3,
                                         uint32_t b0, uint32_t b1) {
    asm volatile("mma.sync.aligned.m16n8k16.row.col.f32.f16.f16.f32 "
                 "{%0,%1,%2,%3}, {%4,%5,%6,%7}, {%8,%9}, {%0,%1,%2,%3};"
                 : "+f"(c[0]), "+f"(c[1]), "+f"(c[2]), "+f"(c[3])
                 : "r"(a0), "r"(a1), "r"(a2), "r"(a3), "r"(b0), "r"(b1));
}
__device__ __forceinline__ void mbar_init(uint32_t a, uint32_t n) {
    asm volatile("mbarrier.init.shared.b64 [%0], %1;" :: "r"(a), "r"(n) : "memory");
}
__device__ __forceinline__ void mbar_expect_tx(uint32_t a, uint32_t bytes) {
    asm volatile("mbarrier.arrive.expect_tx.shared.b64 _, [%0], %1;"
                 :: "r"(a), "r"(bytes) : "memory");
}
__device__ __forceinline__ void mbar_arrive(uint32_t a) {
    asm volatile("mbarrier.arrive.shared.b64 _, [%0];" :: "r"(a) : "memory");
}
__device__ __forceinline__ void mbar_wait(uint32_t mbar, uint32_t parity) {
    uint32_t done;
    asm volatile("{\n\t.reg .pred p;\n\t"
                 "mbarrier.try_wait.parity.acquire.cta.shared::cta.b64 p, [%1], %2;\n\t"
                 "selp.b32 %0, 1, 0, p;\n\t}"
                 : "=r"(done) : "r"(mbar), "r"(parity) : "memory");
    if (!done) {
        asm volatile("{\n\t.reg .pred P1;\n\t"
                     "W%=:\n\t"
                     "mbarrier.try_wait.parity.acquire.cta.shared::cta.b64 P1, [%0], %1, 0x989680;\n\t"
                     "@P1 bra.uni D%=;\n\t"
                     "bra.uni W%=;\n\t"
                     "D%=:\n\t}"
                     :: "r"(mbar), "r"(parity) : "memory");
    }
}
__device__ __forceinline__ void tma3d(uint32_t dst, const void* map,
                                      int c0, int c1, int c2, uint32_t mbar) {
    asm volatile("cp.async.bulk.tensor.3d.shared::cta.global.tile.mbarrier::complete_tx::bytes "
                 "[%0], [%1, {%2, %3, %4}], [%5];"
                 :: "r"(dst), "l"(map), "r"(c0), "r"(c1), "r"(c2), "r"(mbar) : "memory");
}
__device__ __forceinline__ void tma4d(uint32_t dst, const void* map,
                                      int c0, int c1, int c2, int c3, uint32_t mbar) {
    asm volatile("cp.async.bulk.tensor.4d.shared::cta.global.tile.mbarrier::complete_tx::bytes "
                 "[%0], [%1, {%2, %3, %4, %5}], [%6];"
                 :: "r"(dst), "l"(map), "r"(c0), "r"(c1), "r"(c2), "r"(c3), "r"(mbar) : "memory");
}

// ---------------------------------------------------------------------------
// Kernel 1: x -> transposed + halo-padded fp16 [1728 pos][320 ci]
// ---------------------------------------------------------------------------
__global__ void xpad_kernel(const float* __restrict__ x) {
    int i = blockIdx.x * blockDim.x + threadIdx.x;
    if (i >= 1728 * NCH) return;
    int ci = i % NCH, ppos = i / NCH;
    int px = ppos % 12, py = (ppos / 12) % 12, pz = ppos / 144;
    int z = pz - 2, y = py - 2, xx = px - 2;
    float v = 0.f;
    if ((unsigned)z < 8 && (unsigned)y < 8 && (unsigned)xx < 8)
        v = x[ci * VOX + z * 64 + y * 8 + xx];
    gXp[i] = __float2half(v);
}

// ---------------------------------------------------------------------------
// Kernel 2: build equivariant kernel -> gA [tap][och][ci] fp16.
// ---------------------------------------------------------------------------
__global__ void build_kern_kernel(const float* __restrict__ q_in,
                                  const float* __restrict__ q_out,
                                  const float* __restrict__ w_ss,
                                  const float* __restrict__ w_vs,
                                  const float* __restrict__ w_sv,
                                  const float* __restrict__ w_vv0,
                                  const float* __restrict__ w_vv1) {
    int idx = blockIdx.x * blockDim.x + threadIdx.x;
    if (idx >= QN * QN * K3T) return;
    int t = idx % K3T;
    int q = (idx / K3T) % QN;
    int p = idx / (K3T * QN);
    int path = blockIdx.y;

    int dz = t / 25, dy = (t / 5) % 5, dx = t % 5;
    float v0 = (float)(dz - 2) - (q_out[p * 3 + 0] - q_in[q * 3 + 0]);
    float v1 = (float)(dy - 2) - (q_out[p * 3 + 1] - q_in[q * 3 + 1]);
    float v2 = (float)(dx - 2) - (q_out[p * 3 + 2] - q_in[q * 3 + 2]);
    float r  = sqrtf(v0 * v0 + v1 * v1 + v2 * v2);
    float inv = (r > 1e-6f) ? (1.0f / r) : 0.0f;
    float u[3] = {v0 * inv, v1 * inv, v2 * inv};

    const float sigma = 5.5f / 7.0f;
    float R[GK];
#pragma unroll
    for (int g = 0; g < GK; g++) {
        float d = (r - sigma * (float)g) / sigma;
        R[g] = expf(-0.5f * d * d);
    }

    float cross[3][3];
    cross[0][0] = 0.f;    cross[0][1] = -u[2];  cross[0][2] =  u[1];
    cross[1][0] =  u[2];  cross[1][1] = 0.f;    cross[1][2] = -u[0];
    cross[2][0] = -u[1];  cross[2][1] =  u[0];  cross[2][2] = 0.f;

#define KSTORE(row, col, val) \
    gA[((size_t)t * NCH + ((row) * QN + p)) * NCH + ((col) * QN + q)] = __float2half(val)

    if (path == 0) {
        for (int a = 0; a < C0N; a++)
            for (int c = 0; c < C0N; c++) {
                float s = 0.f;
#pragma unroll
                for (int g = 0; g < GK; g++) s += w_ss[(a * C0N + c) * GK + g] * R[g];
                KSTORE(a, c, s);
            }
    } else if (path == 1) {
        for (int a = 0; a < C0N; a++)
            for (int c = 0; c < C1N; c++) {
                float s = 0.f;
#pragma unroll
                for (int g = 0; g < GK; g++) s += w_sv[(a * C1N + c) * GK + g] * R[g];
#pragma unroll
                for (int j = 0; j < 3; j++) KSTORE(a, 8 + c * 3 + j, s * u[j]);
            }
    } else if (path == 2) {
        for (int a = 0; a < C1N; a++)
            for (int c = 0; c < C0N; c++) {
                float s = 0.f;
#pragma unroll
                for (int g = 0; g < GK; g++) s += w_vs[(a * C0N + c) * GK + g] * R[g];
#pragma unroll
                for (int m = 0; m < 3; m++) KSTORE(8 + a * 3 + m, c, s * u[m]);
            }
    } else {
        for (int a = 0; a < C1N; a++)
            for (int c = 0; c < C1N; c++) {
                float d0 = 0.f, d1 = 0.f;
#pragma unroll
                for (int g = 0; g < GK; g++) {
                    d0 += w_vv0[(a * C1N + c) * GK + g] * R[g];
                    d1 += w_vv1[(a * C1N + c) * GK + g] * R[g];
                }
#pragma unroll
                for (int i = 0; i < 3; i++)
#pragma unroll
                    for (int j = 0; j < 3; j++) {
                        float val = ((i == j) ? d0 : 0.f)
                                  + 0.7071067811865476f * d1 * cross[i][j];
                        KSTORE(8 + a * 3 + i, 8 + c * 3 + j, val);
                    }
            }
    }
#undef KSTORE
}

// ---------------------------------------------------------------------------
// Kernel 3: fp16 mma.sync split-K implicit GEMM.
// Producer-warp + full/empty mbarrier pipeline (no __syncthreads in mainloop).
// grid = (10 = 5 M-tiles x 2 N-tiles, NSPL), block = 288:
//   warps 0-7 compute (2Mx4N, 32x64 warp tile), warp 8 = TMA producer.
// full[s]: count 1 (expect_tx);  empty[s]: count 256 (all compute threads).
// ---------------------------------------------------------------------------
__device__ __forceinline__ void issue_chunk(int c, uint32_t sbase, uint32_t mbar,
                                            const void* tA, const void* tB,
                                            int och0, int z0) {
    int t   = c / 5;
    int ci0 = (c - t * 5) * 64;
    int dz = t / 25, r2 = t - dz * 25;
    int dy = r2 / 5, dx = r2 - dy * 5;
    mbar_expect_tx(mbar, STAGE_BYTES);
    tma3d(sbase + SOFF_A, tA, ci0, och0, t, mbar);
    tma4d(sbase + SOFF_B, tB, ci0, dx, dy, z0 + dz, mbar);
}

__global__ void __launch_bounds__(288, 2)
gemm_mma(const __grid_constant__ CUtensorMap tA,
         const __grid_constant__ CUtensorMap tB) {
    extern __shared__ __align__(1024) char smem[];
    const uint32_t sb = smem_u32(smem);
    const int tid = threadIdx.x;
    const int wid = tid >> 5, lane = tid & 31;

    const int mt = blockIdx.x >> 1;          // 0..4
    const int nt = blockIdx.x & 1;           // 0..1
    const int sp = blockIdx.y;
    const int och0 = mt * 64, z0 = nt * 4;
    const int c0 = (sp * NCHUNK) / NSPL;
    const int c1 = ((sp + 1) * NCHUNK) / NSPL;
    const int n  = c1 - c0;

    // mbarriers: full[0], full[1] at sb+0, sb+8; empty[0], empty[1] at sb+16, sb+24
    const uint32_t fullb  = sb;
    const uint32_t emptyb = sb + 16;
    const uint32_t st0 = sb + HDR;

    if (tid == 0) {
        mbar_init(fullb,      1);  mbar_init(fullb + 8,  1);
        mbar_init(emptyb,     256); mbar_init(emptyb + 8, 256);
    }
    asm volatile("fence.proxy.async.shared::cta;" ::: "memory");
    __syncthreads();

    if (wid == 8) {
        // -------- producer warp --------
        if (lane == 0) {
            for (int j = 0; j < n; j++) {
                const int s = j & 1;
                if (j >= NSTG)
                    mbar_wait(emptyb + 8 * s, ((j - NSTG) >> 1) & 1);
                issue_chunk(c0 + j, st0 + (uint32_t)s * STAGE_BYTES,
                            fullb + 8 * s, &tA, &tB, och0, z0);
            }
        }
        return;
    }

    // -------- compute warps (0-7) --------
    const int warp_m = wid >> 2, warp_n = wid & 3;   // 2M x 4N
    const int m0 = warp_m * 32, n0 = warp_n * 64;

    const int quad = lane >> 3, r8 = lane & 7;
    const int a_row = (quad & 1) * 8 + r8;
    const int a_sel = quad >> 1;
    const int b_grp = quad >> 1;
    const int b_sel = quad & 1;
    const uint32_t pa0 = (uint32_t)((m0 + a_row) * 128);
    const uint32_t pa1 = (uint32_t)((m0 + 16 + a_row) * 128);
    uint32_t pb[4];
#pragma unroll
    for (int j2 = 0; j2 < 4; j2++)
        pb[j2] = (uint32_t)((n0 + j2 * 16 + b_grp * 8 + r8) * 128);

    float acc[2][8][4];
#pragma unroll
    for (int mi = 0; mi < 2; mi++)
#pragma unroll
        for (int nj = 0; nj < 8; nj++)
#pragma unroll
            for (int e = 0; e < 4; e++) acc[mi][nj][e] = 0.f;

    for (int i = 0; i < n; i++) {
        const int s = i & 1;
        const uint32_t sbase = st0 + (uint32_t)s * STAGE_BYTES;
        mbar_wait(fullb + 8 * s, (i >> 1) & 1);

#pragma unroll
        for (int g = 0; g < 4; g++) {
            const uint32_t aoff = (uint32_t)((((g << 1) + a_sel) ^ r8) << 4);
            const uint32_t boff = (uint32_t)((((g << 1) + b_sel) ^ r8) << 4);
            uint32_t a0[4], a1[4];
            ldm4(a0[0], a0[1], a0[2], a0[3], sbase + SOFF_A + pa0 + aoff);
            ldm4(a1[0], a1[1], a1[2], a1[3], sbase + SOFF_A + pa1 + aoff);
#pragma unroll
            for (int j2 = 0; j2 < 4; j2++) {
                uint32_t b[4];
                ldm4(b[0], b[1], b[2], b[3], sbase + SOFF_B + pb[j2] + boff);
                mma16816(acc[0][2 * j2],     a0[0], a0[1], a0[2], a0[3], b[0], b[1]);
                mma16816(acc[0][2 * j2 + 1], a0[0], a0[1], a0[2], a0[3], b[2], b[3]);
                mma16816(acc[1][2 * j2],     a1[0], a1[1], a1[2], a1[3], b[0], b[1]);
                mma16816(acc[1][2 * j2 + 1], a1[0], a1[1], a1[2], a1[3], b[2], b[3]);
            }
        }
        mbar_arrive(emptyb + 8 * s);   // every compute thread arrives (count 256)
    }

    // epilogue -> g_part[sp][blockIdx.x][64][256]
    float* dst = g_part + (size_t)(sp * 10 + blockIdx.x) * (64 * 256);
    const int gidx = lane >> 2, tid4 = lane & 3;
#pragma unroll
    for (int mi = 0; mi < 2; mi++)
#pragma unroll
        for (int nj = 0; nj < 8; nj++) {
            int row = m0 + 16 * mi + gidx;
            int col = n0 + 8 * nj + tid4 * 2;
            *(float2*)(dst + row * 256 + col) =
                make_float2(acc[mi][nj][0], acc[mi][nj][1]);
            *(float2*)(dst + (row + 8) * 256 + col) =
                make_float2(acc[mi][nj][2], acc[mi][nj][3]);
        }
}

// ---------------------------------------------------------------------------
// Kernel 4: reduce split partials + bias (float4 vectorized).
// ---------------------------------------------------------------------------
__global__ void reduce_kernel(float* __restrict__ out,
                              const float* __restrict__ bias) {
    int idx = blockIdx.x * blockDim.x + threadIdx.x;   // one float4 per thread
    if (idx >= NCH * VOX / 4) return;
    int i = idx * 4;
    int och = i >> 9, v = i & 511;
    int mt = och >> 6, ro = och & 63;
    int ntl = v >> 8, rv = v & 255;
    int blk = mt * 2 + ntl;
    const float* src = g_part + (size_t)blk * (64 * 256) + ro * 256 + rv;
    float4 s = make_float4(0.f, 0.f, 0.f, 0.f);
#pragma unroll
    for (int sp = 0; sp < NSPL; sp++) {
        float4 t = *(const float4*)(src + (size_t)sp * 10 * 64 * 256);
        s.x += t.x; s.y += t.y; s.z += t.z; s.w += t.w;
    }
    int d = och >> 4;
    if (d < C0N) {
        float b = bias[d];
        s.x += b; s.y += b; s.z += b; s.w += b;
    }
    *(float4*)(out + i) = s;
}

// ---------------------------------------------------------------------------
typedef CUresult (*EncodeFn)(CUtensorMap*, CUtensorMapDataType, cuuint32_t, void*,
                             const cuuint64_t*, const cuuint64_t*, const cuuint32_t*,
                             const cuuint32_t*, CUtensorMapInterleave, CUtensorMapSwizzle,
                             CUtensorMapL2promotion, CUtensorMapFloatOOBfill);

static void make_map_3d(EncodeFn enc, CUtensorMap* m, void* base) {
    cuuint64_t dims[3]    = {NCH, NCH, K3T};
    cuuint64_t strides[2] = {NCH * 2ull, (cuuint64_t)NCH * NCH * 2ull};
    cuuint32_t box[3]     = {64, 64, 1};
    cuuint32_t es[3]      = {1, 1, 1};
    enc(m, CU_TENSOR_MAP_DATA_TYPE_FLOAT16, 3, base, dims, strides, box, es,
        CU_TENSOR_MAP_INTERLEAVE_NONE, CU_TENSOR_MAP_SWIZZLE_128B,
        CU_TENSOR_MAP_L2_PROMOTION_L2_128B, CU_TENSOR_MAP_FLOAT_OOB_FILL_NONE);
}
static void make_map_4d(EncodeFn enc, CUtensorMap* m, void* base) {
    cuuint64_t dims[4]    = {NCH, 12, 12, 12};
    cuuint64_t strides[3] = {NCH * 2ull, NCH * 12 * 2ull, NCH * 144 * 2ull};
    cuuint32_t box[4]     = {64, 8, 8, 4};
    cuuint32_t es[4]      = {1, 1, 1, 1};
    enc(m, CU_TENSOR_MAP_DATA_TYPE_FLOAT16, 4, base, dims, strides, box, es,
        CU_TENSOR_MAP_INTERLEAVE_NONE, CU_TENSOR_MAP_SWIZZLE_128B,
        CU_TENSOR_MAP_L2_PROMOTION_L2_128B, CU_TENSOR_MAP_FLOAT_OOB_FILL_NONE);
}

extern "C" void kernel_launch(void* const* d_in, const int* in_sizes, int n_in,
                              void* d_out, int out_size) {
    const float* x     = (const float*)d_in[0];
    const float* q_in  = (const float*)d_in[1];
    const float* q_out = (const float*)d_in[2];
    const float* w_ss  = (const float*)d_in[3];
    const float* w_vs  = (const float*)d_in[4];
    const float* w_sv  = (const float*)d_in[5];
    const float* w_vv0 = (const float*)d_in[6];
    const float* w_vv1 = (const float*)d_in[7];
    const float* bias  = (const float*)d_in[8];
    float* out = (float*)d_out;

    void* lib = dlopen("libcuda.so.1", RTLD_LAZY | RTLD_GLOBAL);
    EncodeFn enc = lib ? (EncodeFn)dlsym(lib, "cuTensorMapEncodeTiled") : nullptr;

    void *pA, *pB;
    cudaGetSymbolAddress(&pA, gA);
    cudaGetSymbolAddress(&pB, gXp);

    CUtensorMap mA, mB;
    make_map_3d(enc, &mA, pA);
    make_map_4d(enc, &mB, pB);

    xpad_kernel<<<(1728 * NCH + 255) / 256, 256>>>(x);

    dim3 bgrid((QN * QN * K3T + 255) / 256, 4);
    build_kern_kernel<<<bgrid, 256>>>(q_in, q_out, w_ss, w_vs, w_sv, w_vv0, w_vv1);

    cudaFuncSetAttribute(gemm_mma, cudaFuncAttributeMaxDynamicSharedMemorySize, SMEM_TOTAL);
    gemm_mma<<<dim3(10, NSPL), 288, SMEM_TOTAL>>>(mA, mB);

    reduce_kernel<<<(NCH * VOX / 4 + 255) / 256, 256>>>(out, bias);
}